// round 17
// baseline (speedup 1.0000x reference)
#include <cuda_runtime.h>
#include <cuda_fp16.h>
#include <math.h>
#include <stdint.h>

#define HW 16384
#define IMG_W 128
#define DIM 192
#define HEADS 4
#define DHEAD 48
#define HIDDEN 510
#define BATCH 4
#define NPART 8

// ---------------- scratch (static device arrays) --------------------------------
__device__ __half g_S0h[BATCH * 1020 * HW]; // conv1x1 outputs
__device__ __half g_S1h[BATCH * 576 * HW];  // dw qkv out (576) / gated gdfn (512 pad)
__device__ __half g_S2h[BATCH * DIM * HW];  // LN xhat / attn output
__device__ __half g_S3h[BATCH * DIM * HW];  // proj fp16 copy (ln2 source)
__device__ __half g_Wqkv[576 * 192];
__device__ __half g_Wproj[192 * 192];
__device__ __half g_Wpin[1024 * 192];       // padded 1020->1024
__device__ __half g_Wpout[192 * 512];       // padded K 510->512
__device__ float g_rnpart[NPART * BATCH * 2 * DIM]; // [p][r]
__device__ float g_A[16 * DHEAD * DHEAD];
__device__ float g_Apart[16 * 16 * DHEAD * DHEAD];

// ---------------- helpers -------------------------------------------------------
__device__ __forceinline__ uint32_t pack_h2(float x, float y) {
    __half2 h = __floats2half2_rn(x, y);
    return *(uint32_t*)&h;
}
__device__ __forceinline__ uint32_t sm_addr(const void* p) {
    return (uint32_t)__cvta_generic_to_shared(p);
}
__device__ __forceinline__ void ldsm_x4(uint32_t* r, uint32_t addr) {
    asm volatile("ldmatrix.sync.aligned.m8n8.x4.shared.b16 {%0,%1,%2,%3}, [%4];"
        : "=r"(r[0]), "=r"(r[1]), "=r"(r[2]), "=r"(r[3]) : "r"(addr));
}
__device__ __forceinline__ void ldsm_x4t(uint32_t* r, uint32_t addr) {
    asm volatile("ldmatrix.sync.aligned.m8n8.x4.trans.shared.b16 {%0,%1,%2,%3}, [%4];"
        : "=r"(r[0]), "=r"(r[1]), "=r"(r[2]), "=r"(r[3]) : "r"(addr));
}
__device__ __forceinline__ void ldsm_x2(uint32_t* r, uint32_t addr) {
    asm volatile("ldmatrix.sync.aligned.m8n8.x2.shared.b16 {%0,%1}, [%2];"
        : "=r"(r[0]), "=r"(r[1]) : "r"(addr));
}
__device__ __forceinline__ void mma_f16acc(uint32_t* d, const uint32_t* a, const uint32_t* b) {
    asm volatile("mma.sync.aligned.m16n8k16.row.col.f16.f16.f16.f16 "
        "{%0,%1}, {%2,%3,%4,%5}, {%6,%7}, {%0,%1};"
        : "+r"(d[0]), "+r"(d[1])
        : "r"(a[0]), "r"(a[1]), "r"(a[2]), "r"(a[3]), "r"(b[0]), "r"(b[1]));
}
__device__ __forceinline__ void mma_f32acc(float* d, const uint32_t* a, const uint32_t* b) {
    asm volatile("mma.sync.aligned.m16n8k16.row.col.f32.f16.f16.f32 "
        "{%0,%1,%2,%3}, {%4,%5,%6,%7}, {%8,%9}, {%0,%1,%2,%3};"
        : "+f"(d[0]), "+f"(d[1]), "+f"(d[2]), "+f"(d[3])
        : "r"(a[0]), "r"(a[1]), "r"(a[2]), "r"(a[3]), "r"(b[0]), "r"(b[1]));
}
__device__ __forceinline__ void cpa16(uint32_t dst, const void* src) {
    asm volatile("cp.async.cg.shared.global [%0], [%1], 16;" :: "r"(dst), "l"(src));
}
__device__ __forceinline__ void cpa_commit() { asm volatile("cp.async.commit_group;"); }
template<int N> __device__ __forceinline__ void cpa_wait() {
    asm volatile("cp.async.wait_group %0;" :: "n"(N));
}

// ---------------- weight fp32 -> fp16 with padding ------------------------------
__global__ __launch_bounds__(256) void wconv_kernel(const float* __restrict__ src,
                                                    __half* __restrict__ dst,
                                                    int M, int K, int Mp, int Kp) {
    int idx = blockIdx.x * 256 + threadIdx.x;
    int tot = Mp * Kp;
    if (idx >= tot) return;
    int m = idx / Kp, k = idx - m * Kp;
    float v = (m < M && k < K) ? src[m * K + k] : 0.f;
    dst[idx] = __float2half(v);
}

// ---------------- LN from fp32 input (per batch) --------------------------------
__global__ __launch_bounds__(256) void ln_apply_kernel(const float* __restrict__ x,
                                                       const float* __restrict__ lnW,
                                                       __half* __restrict__ xh, int b) {
    __shared__ float sw[DIM];
    int tid = threadIdx.x;
    if (tid < DIM) sw[tid] = lnW[tid];
    __syncthreads();
    int n = blockIdx.x * 256 + tid;
    const float* xb = x + (long long)b * DIM * HW + n;
    float s = 0.f, s2 = 0.f;
#pragma unroll 8
    for (int c = 0; c < DIM; c++) {
        float v = xb[(long long)c * HW];
        s += v; s2 += v * v;
    }
    float m = s * (1.f / DIM);
    float var = s2 * (1.f / DIM) - m * m;
    float inv = rsqrtf(var + 1e-6f);
    __half* ob = xh + (long long)b * DIM * HW + n;
#pragma unroll 8
    for (int c = 0; c < DIM; c++)
        ob[(long long)c * HW] = __float2half((xb[(long long)c * HW] - m) * inv * sw[c]);
}

// ---------------- LN from fp16 input (ln2 path, per batch) ----------------------
__global__ __launch_bounds__(256) void ln_apply_h_kernel(const __half* __restrict__ x,
                                                         const float* __restrict__ lnW,
                                                         __half* __restrict__ xh, int b) {
    __shared__ float sw[DIM];
    int tid = threadIdx.x;
    if (tid < DIM) sw[tid] = lnW[tid];
    __syncthreads();
    int n = blockIdx.x * 256 + tid;
    const __half* xb = x + (long long)b * DIM * HW + n;
    float s = 0.f, s2 = 0.f;
#pragma unroll 8
    for (int c = 0; c < DIM; c++) {
        float v = __half2float(xb[(long long)c * HW]);
        s += v; s2 += v * v;
    }
    float m = s * (1.f / DIM);
    float var = s2 * (1.f / DIM) - m * m;
    float inv = rsqrtf(var + 1e-6f);
    __half* ob = xh + (long long)b * DIM * HW + n;
#pragma unroll 8
    for (int c = 0; c < DIM; c++) {
        float v = __half2float(xb[(long long)c * HW]);
        ob[(long long)c * HW] = __float2half((v - m) * inv * sw[c]);
    }
}

// ---------------- fp16 GEMM: BM=64, BN=256, BK=32, 128 thr ----------------------
#define ASTR 40
#define BSTR 264

__global__ __launch_bounds__(128, 4) void gemm_fp16(const __half* __restrict__ Wb,
                                                    const __half* __restrict__ X,
                                                    void* __restrict__ Outv,
                                                    const float* __restrict__ Res,
                                                    __half* __restrict__ OutCopy,
                                                    int M, int K,
                                                    long long xbs, long long obs,
                                                    int outF16, int addRes, int b) {
    __shared__ __align__(16) __half As[2][64][ASTR];
    __shared__ __align__(16) __half Bs[2][32][BSTR];
    int tid = threadIdx.x, lane = tid & 31, wn = tid >> 5;
    int ra = lane >> 2, ca = lane & 3;
    int n0 = blockIdx.x * 256;
    int m0 = blockIdx.y * 64;
    const __half* Xb = X + (long long)b * xbs;

    uint32_t acc[4][8][2];
#pragma unroll
    for (int i = 0; i < 4; i++)
#pragma unroll
        for (int j = 0; j < 8; j++) { acc[i][j][0] = 0u; acc[i][j][1] = 0u; }

    int nk = K >> 5;

    auto load_slab = [&](int kt, int s) {
        int kb = kt << 5;
#pragma unroll
        for (int i = 0; i < 2; i++) {
            int id = tid + i * 128;
            int m = id >> 2, kc = (id & 3) * 8;
            cpa16(sm_addr(&As[s][m][kc]), &Wb[(long long)(m0 + m) * K + kb + kc]);
        }
#pragma unroll
        for (int i = 0; i < 8; i++) {
            int id = tid + i * 128;
            int kr = id >> 5, nc = (id & 31) * 8;
            cpa16(sm_addr(&Bs[s][kr][nc]), &Xb[(long long)(kb + kr) * HW + n0 + nc]);
        }
    };

    load_slab(0, 0);
    cpa_commit();

    for (int kt = 0; kt < nk; kt++) {
        if (kt + 1 < nk) load_slab(kt + 1, (kt + 1) & 1);
        cpa_commit();
        cpa_wait<1>();
        __syncthreads();
        int s = kt & 1;
#pragma unroll
        for (int ks = 0; ks < 2; ks++) {
            uint32_t afr[4][4], bfr[8][2];
#pragma unroll
            for (int tm = 0; tm < 4; tm++)
                ldsm_x4(afr[tm], sm_addr(&As[s][tm * 16 + (lane & 15)]
                                            [ks * 16 + (lane >> 4) * 8]));
#pragma unroll
            for (int tnp = 0; tnp < 4; tnp++) {
                uint32_t t4[4];
                ldsm_x4t(t4, sm_addr(&Bs[s][ks * 16 + (lane & 15)]
                                        [wn * 64 + tnp * 16 + (lane >> 4) * 8]));
                bfr[2 * tnp][0] = t4[0]; bfr[2 * tnp][1] = t4[1];
                bfr[2 * tnp + 1][0] = t4[2]; bfr[2 * tnp + 1][1] = t4[3];
            }
#pragma unroll
            for (int tm = 0; tm < 4; tm++)
#pragma unroll
                for (int tn = 0; tn < 8; tn++)
                    mma_f16acc(acc[tm][tn], afr[tm], bfr[tn]);
        }
        __syncthreads();
    }

    if (outF16) {
        __half* Ob = (__half*)Outv + (long long)b * obs;
#pragma unroll
        for (int tm = 0; tm < 4; tm++)
#pragma unroll
            for (int tn = 0; tn < 8; tn++) {
                int col = n0 + wn * 64 + tn * 8 + 2 * ca;
                int r0 = m0 + tm * 16 + ra;
                int r1 = r0 + 8;
                if (r0 < M) *(uint32_t*)&Ob[(long long)r0 * HW + col] = acc[tm][tn][0];
                if (r1 < M) *(uint32_t*)&Ob[(long long)r1 * HW + col] = acc[tm][tn][1];
            }
    } else {
        float* Ob = (float*)Outv + (long long)b * obs;
        const float* Rb = Res + (long long)b * obs;
        __half* Cb = OutCopy ? OutCopy + (long long)b * obs : nullptr;
#pragma unroll
        for (int tm = 0; tm < 4; tm++)
#pragma unroll
            for (int tn = 0; tn < 8; tn++) {
                int col = n0 + wn * 64 + tn * 8 + 2 * ca;
                int r0 = m0 + tm * 16 + ra;
                int r1 = r0 + 8;
                if (r0 < M) {
                    float2 v = __half22float2(*(__half2*)&acc[tm][tn][0]);
                    long long off = (long long)r0 * HW + col;
                    if (addRes) { float2 rr = *(const float2*)&Rb[off]; v.x += rr.x; v.y += rr.y; }
                    *(float2*)&Ob[off] = v;
                    if (Cb) *(uint32_t*)&Cb[off] = pack_h2(v.x, v.y);
                }
                if (r1 < M) {
                    float2 v = __half22float2(*(__half2*)&acc[tm][tn][1]);
                    long long off = (long long)r1 * HW + col;
                    if (addRes) { float2 rr = *(const float2*)&Rb[off]; v.x += rr.x; v.y += rr.y; }
                    *(float2*)&Ob[off] = v;
                    if (Cb) *(uint32_t*)&Cb[off] = pack_h2(v.x, v.y);
                }
            }
    }
}

// ---------------- depthwise 3x3 qkv (per batch) ---------------------------------
__global__ __launch_bounds__(256) void dw_qkv_kernel(const __half* __restrict__ in,
                                                     const float* __restrict__ w9,
                                                     __half* __restrict__ out, int b) {
    __shared__ __half st[18][136];
    __shared__ float red[256];
    int c = blockIdx.y;
    long long base = ((long long)b * 576 + c) * HW;
    const __half* ib = in + base;
    int y0 = blockIdx.x * 16;
    int tid = threadIdx.x;
    float w[9];
#pragma unroll
    for (int i = 0; i < 9; i++) w[i] = w9[c * 9 + i];

    for (int id = tid; id < 288; id += 256) {
        int r = id >> 4, c8 = (id & 15) * 8;
        int gy = y0 - 1 + r;
        uint4 v = make_uint4(0u, 0u, 0u, 0u);
        if ((unsigned)gy < IMG_W) v = *(const uint4*)&ib[gy * IMG_W + c8];
        *(uint4*)&st[r][c8] = v;
    }
    __syncthreads();

    int r = tid >> 4, x0 = (tid & 15) * 8;
    float o[8] = {};
#pragma unroll
    for (int ky = 0; ky < 3; ky++) {
        float t[10];
#pragma unroll
        for (int i = 0; i < 10; i++) {
            int xx = x0 - 1 + i;
            t[i] = ((unsigned)xx < IMG_W) ? __half2float(st[r + ky][xx]) : 0.f;
        }
        float w0 = w[ky * 3], w1 = w[ky * 3 + 1], w2 = w[ky * 3 + 2];
#pragma unroll
        for (int j = 0; j < 8; j++)
            o[j] += w0 * t[j] + w1 * t[j + 1] + w2 * t[j + 2];
    }
    uint4 pv;
    uint32_t* pp = (uint32_t*)&pv;
#pragma unroll
    for (int i = 0; i < 4; i++) pp[i] = pack_h2(o[2 * i], o[2 * i + 1]);
    *(uint4*)&out[base + (y0 + r) * IMG_W + x0] = pv;

    if (c < 384) {
        float ss = 0.f;
#pragma unroll
        for (int j = 0; j < 8; j++) ss += o[j] * o[j];
        red[tid] = ss;
        __syncthreads();
        for (int stp = 128; stp; stp >>= 1) {
            if (tid < stp) red[tid] += red[tid + stp];
            __syncthreads();
        }
        if (tid == 0)
            g_rnpart[(long long)blockIdx.x * (BATCH * 384) + b * 384 + c] = red[0];
    }
}

// ---------------- split-K partial Q.K^T (per batch) -----------------------------
__global__ __launch_bounds__(256) void attn_part_kernel(int b) {
    __shared__ __align__(16) __half Qs[48][72];
    __shared__ __align__(16) __half Ks[48][72];
    int chunk = blockIdx.x;
    int h = blockIdx.y;
    int bh = b * 4 + h;
    const __half* qb = g_S1h + ((long long)b * 576 + h * DHEAD) * HW;
    const __half* kb = g_S1h + ((long long)b * 576 + DIM + h * DHEAD) * HW;
    int tid = threadIdx.x, lane = tid & 31, w = tid >> 5;
    int mt = w >> 1, nh = w & 1;
    int ra = lane >> 2, ca = lane & 3;
    long long nbase = (long long)chunk * 1024;

    float acc[3][4] = {};

    for (int sl = 0; sl < 16; sl++) {
        long long nb = nbase + sl * 64;
#pragma unroll
        for (int i = 0; i < 3; i++) {
            int id = tid + i * 256;
            int r = id >> 3;
            int c8 = (id & 7) * 8;
            if (r < 48)
                cpa16(sm_addr(&Qs[r][c8]), &qb[(long long)r * HW + nb + c8]);
            else
                cpa16(sm_addr(&Ks[r - 48][c8]), &kb[(long long)(r - 48) * HW + nb + c8]);
        }
        cpa_commit();
        cpa_wait<0>();
        __syncthreads();
        if (w < 6) {
#pragma unroll
            for (int kp = 0; kp < 4; kp++) {
                uint32_t afr[4], bfr[3][2];
                ldsm_x4(afr, sm_addr(&Qs[mt * 16 + (lane & 15)][kp * 16 + (lane >> 4) * 8]));
#pragma unroll
                for (int tn = 0; tn < 3; tn++)
                    ldsm_x2(bfr[tn], sm_addr(&Ks[nh * 24 + tn * 8 + (lane & 7)]
                                                [kp * 16 + ((lane >> 3) & 1) * 8]));
#pragma unroll
                for (int tn = 0; tn < 3; tn++)
                    mma_f32acc(acc[tn], afr, bfr[tn]);
            }
        }
        __syncthreads();
    }
    if (w < 6) {
        float* P = g_Apart + ((long long)bh * 16 + chunk) * (DHEAD * DHEAD);
#pragma unroll
        for (int tn = 0; tn < 3; tn++) {
            int d0 = nh * 24 + tn * 8 + 2 * ca;
            int c0 = mt * 16 + ra;
            *(float2*)&P[c0 * DHEAD + d0] = make_float2(acc[tn][0], acc[tn][1]);
            *(float2*)&P[(c0 + 8) * DHEAD + d0] = make_float2(acc[tn][2], acc[tn][3]);
        }
    }
}

// ---------------- reduce partials + rownorms, scale, softmax (per batch) --------
__global__ __launch_bounds__(256) void attn_finish_kernel(const float* __restrict__ temp,
                                                          int b) {
    int h = blockIdx.x;
    int bh = b * 4 + h;
    __shared__ float sA[DHEAD * DHEAD];
    __shared__ float srn_q[DHEAD], srn_k[DHEAD];
    int tid = threadIdx.x;
    if (tid < 96) {
        int i = tid;
        int isK = (i >= DHEAD);
        int cc = i - isK * DHEAD;
        int row = b * 384 + isK * DIM + h * DHEAD + cc;
        float s = 0.f;
#pragma unroll
        for (int p = 0; p < NPART; p++) s += g_rnpart[(long long)p * (BATCH * 384) + row];
        float v = 1.f / fmaxf(sqrtf(s), 1e-12f);
        if (isK) srn_k[cc] = v; else srn_q[cc] = v;
    }
    __syncthreads();
    for (int i = tid; i < DHEAD * DHEAD; i += 256) {
        float s = 0.f;
        for (int p = 0; p < 16; p++)
            s += g_Apart[((long long)bh * 16 + p) * (DHEAD * DHEAD) + i];
        int c = i / DHEAD, d = i % DHEAD;
        sA[i] = s * srn_q[c] * srn_k[d] * temp[h];
    }
    __syncthreads();
    if (tid < DHEAD) {
        float mx = -1e30f;
        for (int d = 0; d < DHEAD; d++) mx = fmaxf(mx, sA[tid * DHEAD + d]);
        float sum = 0.f;
        for (int d = 0; d < DHEAD; d++) sum += __expf(sA[tid * DHEAD + d] - mx);
        float inv = 1.f / sum;
        for (int d = 0; d < DHEAD; d++)
            g_A[bh * DHEAD * DHEAD + tid * DHEAD + d] =
                __expf(sA[tid * DHEAD + d] - mx) * inv;
    }
}

// ---------------- out = A @ V via tensor cores (per batch) ----------------------
__global__ __launch_bounds__(256) void av_kernel(int b) {
    __shared__ __align__(16) __half Ab[48][56];
    __shared__ __align__(16) __half Vs[48][264];
    int h = blockIdx.y;
    int bh = b * 4 + h;
    int tid = threadIdx.x, lane = tid & 31, wn = tid >> 5;
    int ra = lane >> 2, ca = lane & 3;
    int n0 = blockIdx.x * 256;

    for (int i = tid; i < DHEAD * DHEAD; i += 256)
        Ab[i / DHEAD][i % DHEAD] = __float2half(g_A[bh * DHEAD * DHEAD + i]);

    const __half* vb = g_S1h + ((long long)b * 576 + 2 * DIM + h * DHEAD) * HW;
#pragma unroll
    for (int i = 0; i < 6; i++) {
        int id = tid + i * 256;
        int d = id >> 5, c8 = (id & 31) * 8;
        cpa16(sm_addr(&Vs[d][c8]), &vb[(long long)d * HW + n0 + c8]);
    }
    cpa_commit();
    cpa_wait<0>();
    __syncthreads();

    float acc[3][4][4];
#pragma unroll
    for (int i = 0; i < 3; i++)
#pragma unroll
        for (int j = 0; j < 4; j++)
#pragma unroll
            for (int q = 0; q < 4; q++) acc[i][j][q] = 0.f;

#pragma unroll
    for (int ks = 0; ks < 3; ks++) {
        uint32_t afr[3][4], bfr[4][2];
#pragma unroll
        for (int mt = 0; mt < 3; mt++)
            ldsm_x4(afr[mt], sm_addr(&Ab[mt * 16 + (lane & 15)][ks * 16 + (lane >> 4) * 8]));
#pragma unroll
        for (int tnp = 0; tnp < 2; tnp++) {
            uint32_t t4[4];
            ldsm_x4t(t4, sm_addr(&Vs[ks * 16 + (lane & 15)]
                                    [wn * 32 + tnp * 16 + (lane >> 4) * 8]));
            bfr[2 * tnp][0] = t4[0]; bfr[2 * tnp][1] = t4[1];
            bfr[2 * tnp + 1][0] = t4[2]; bfr[2 * tnp + 1][1] = t4[3];
        }
#pragma unroll
        for (int mt = 0; mt < 3; mt++)
#pragma unroll
            for (int tn = 0; tn < 4; tn++)
                mma_f32acc(acc[mt][tn], afr[mt], bfr[tn]);
    }

    __half* ob = g_S2h + ((long long)b * DIM + h * DHEAD) * HW;
#pragma unroll
    for (int mt = 0; mt < 3; mt++)
#pragma unroll
        for (int tn = 0; tn < 4; tn++) {
            int col = n0 + wn * 32 + tn * 8 + 2 * ca;
            int c0 = mt * 16 + ra;
            *(uint32_t*)&ob[(long long)c0 * HW + col] =
                pack_h2(acc[mt][tn][0], acc[mt][tn][1]);
            *(uint32_t*)&ob[(long long)(c0 + 8) * HW + col] =
                pack_h2(acc[mt][tn][2], acc[mt][tn][3]);
        }
}

// ---------------- fused GDFN dw3x3 + GELU gate (per batch) ----------------------
__global__ __launch_bounds__(256) void dw_gate_kernel(const __half* __restrict__ in,
                                                      const float* __restrict__ w9,
                                                      __half* __restrict__ out, int b) {
    __shared__ __half st1[18][136], st2[18][136];
    int c = blockIdx.y;
    int y0 = blockIdx.x * 16;
    int tid = threadIdx.x;
    int r = tid >> 4, x0 = (tid & 15) * 8;
    long long obase = ((long long)b * 512 + c) * HW;

    if (c >= HIDDEN) {
        uint4 z = make_uint4(0u, 0u, 0u, 0u);
        *(uint4*)&out[obase + (y0 + r) * IMG_W + x0] = z;
        return;
    }
    long long base1 = ((long long)b * 1020 + c) * HW;
    long long base2 = ((long long)b * 1020 + HIDDEN + c) * HW;
    float w1[9], w2[9];
#pragma unroll
    for (int i = 0; i < 9; i++) { w1[i] = w9[c * 9 + i]; w2[i] = w9[(HIDDEN + c) * 9 + i]; }

    for (int id = tid; id < 288; id += 256) {
        int rr = id >> 4, c8 = (id & 15) * 8;
        int gy = y0 - 1 + rr;
        uint4 v1 = make_uint4(0u, 0u, 0u, 0u), v2 = v1;
        if ((unsigned)gy < IMG_W) {
            v1 = *(const uint4*)&in[base1 + gy * IMG_W + c8];
            v2 = *(const uint4*)&in[base2 + gy * IMG_W + c8];
        }
        *(uint4*)&st1[rr][c8] = v1;
        *(uint4*)&st2[rr][c8] = v2;
    }
    __syncthreads();

    float o1[8] = {}, o2[8] = {};
#pragma unroll
    for (int ky = 0; ky < 3; ky++) {
        float t1[10], t2[10];
#pragma unroll
        for (int i = 0; i < 10; i++) {
            int xx = x0 - 1 + i;
            bool ok = (unsigned)xx < IMG_W;
            t1[i] = ok ? __half2float(st1[r + ky][xx]) : 0.f;
            t2[i] = ok ? __half2float(st2[r + ky][xx]) : 0.f;
        }
        float a0 = w1[ky * 3], a1 = w1[ky * 3 + 1], a2 = w1[ky * 3 + 2];
        float b0 = w2[ky * 3], b1 = w2[ky * 3 + 1], b2 = w2[ky * 3 + 2];
#pragma unroll
        for (int j = 0; j < 8; j++) {
            o1[j] += a0 * t1[j] + a1 * t1[j + 1] + a2 * t1[j + 2];
            o2[j] += b0 * t2[j] + b1 * t2[j + 1] + b2 * t2[j + 2];
        }
    }
    uint4 pv;
    uint32_t* pp = (uint32_t*)&pv;
#pragma unroll
    for (int i = 0; i < 4; i++) {
        float g0 = 0.5f * o1[2 * i] * (1.f + erff(o1[2 * i] * 0.70710678118654752f));
        float g1 = 0.5f * o1[2 * i + 1] * (1.f + erff(o1[2 * i + 1] * 0.70710678118654752f));
        pp[i] = pack_h2(g0 * o2[2 * i], g1 * o2[2 * i + 1]);
    }
    *(uint4*)&out[obase + (y0 + r) * IMG_W + x0] = pv;
}

// =============================================================================
extern "C" void kernel_launch(void* const* d_in, const int* in_sizes, int n_in,
                              void* d_out, int out_size) {
    const float* x     = (const float*)d_in[0];
    const float* n1w   = (const float*)d_in[1];
    const float* qkvw  = (const float*)d_in[2];
    const float* qkvdw = (const float*)d_in[3];
    const float* temp  = (const float*)d_in[4];
    const float* projw = (const float*)d_in[5];
    const float* n2w   = (const float*)d_in[6];
    const float* pinw  = (const float*)d_in[7];
    const float* dww   = (const float*)d_in[8];
    const float* poutw = (const float*)d_in[9];
    float* out = (float*)d_out;

    __half *S0h, *S1h, *S2h, *S3h, *Wqkv, *Wproj, *Wpin, *Wpout;
    cudaGetSymbolAddress((void**)&S0h, g_S0h);
    cudaGetSymbolAddress((void**)&S1h, g_S1h);
    cudaGetSymbolAddress((void**)&S2h, g_S2h);
    cudaGetSymbolAddress((void**)&S3h, g_S3h);
    cudaGetSymbolAddress((void**)&Wqkv, g_Wqkv);
    cudaGetSymbolAddress((void**)&Wproj, g_Wproj);
    cudaGetSymbolAddress((void**)&Wpin, g_Wpin);
    cudaGetSymbolAddress((void**)&Wpout, g_Wpout);

    // weight conversions once
    wconv_kernel<<<(576 * 192 + 255) / 256, 256>>>(qkvw, Wqkv, 576, 192, 576, 192);
    wconv_kernel<<<(192 * 192 + 255) / 256, 256>>>(projw, Wproj, 192, 192, 192, 192);
    wconv_kernel<<<(1024 * 192 + 255) / 256, 256>>>(pinw, Wpin, 1020, 192, 1024, 192);
    wconv_kernel<<<(192 * 512 + 255) / 256, 256>>>(poutw, Wpout, 192, 510, 192, 512);

    // per-batch pipeline: every producer->consumer hand-off stays L2-resident
    for (int b = 0; b < BATCH; b++) {
        // ---- MDTA ----
        ln_apply_kernel<<<HW / 256, 256>>>(x, n1w, S2h, b);
        gemm_fp16<<<dim3(HW / 256, 9), 128>>>(
            Wqkv, S2h, S0h, nullptr, nullptr,
            576, 192, (long long)DIM * HW, (long long)576 * HW, 1, 0, b);
        dw_qkv_kernel<<<dim3(NPART, 576), 256>>>(S0h, qkvdw, S1h, b);
        attn_part_kernel<<<dim3(16, 4), 256>>>(b);
        attn_finish_kernel<<<4, 256>>>(temp, b);
        av_kernel<<<dim3(HW / 256, 4), 256>>>(b);
        gemm_fp16<<<dim3(HW / 256, 3), 128>>>(
            Wproj, S2h, out, x, S3h,
            192, 192, (long long)DIM * HW, (long long)DIM * HW, 0, 1, b);

        // ---- GDFN ----
        ln_apply_h_kernel<<<HW / 256, 256>>>(S3h, n2w, S2h, b);
        gemm_fp16<<<dim3(HW / 256, 16), 128>>>(
            Wpin, S2h, S0h, nullptr, nullptr,
            1020, 192, (long long)DIM * HW, (long long)1020 * HW, 1, 0, b);
        dw_gate_kernel<<<dim3(NPART, 512), 256>>>(S0h, dww, S1h, b);
        gemm_fp16<<<dim3(HW / 256, 3), 128>>>(
            Wpout, S1h, out, out, nullptr,
            192, 512, (long long)512 * HW, (long long)DIM * HW, 0, 1, b);
    }
}